// round 1
// baseline (speedup 1.0000x reference)
#include <cuda_runtime.h>

// db2 filter constants
#define DL0 (-0.12940952255092145f)
#define DL1 ( 0.22414386804185735f)
#define DL2 ( 0.836516303737469f)
#define DL3 ( 0.48296291314469025f)
#define DH0 (-0.48296291314469025f)
#define DH1 ( 0.836516303737469f)
#define DH2 (-0.22414386804185735f)
#define DH3 (-0.12940952255092145f)
#define RL0 ( 0.48296291314469025f)
#define RL1 ( 0.836516303737469f)
#define RL2 ( 0.22414386804185735f)
#define RL3 (-0.12940952255092145f)
#define RH0 (-0.12940952255092145f)
#define RH1 (-0.22414386804185735f)
#define RH2 ( 0.836516303737469f)
#define RH3 (-0.48296291314469025f)

static constexpr int D   = 512;   // row length
static constexpr int TPR = 128;   // threads per row (512/4)
static constexpr int RPB = 2;     // rows per block
static constexpr int EXT = 520;   // 516 used + pad (keeps 16B alignment: 520*4=2080 bytes)

__global__ __launch_bounds__(TPR * RPB)
void wavelet_db2_fused_kernel(const float* __restrict__ x,
                              const float* __restrict__ weight,
                              float* __restrict__ out)
{
    __shared__ __align__(16) float e[RPB][EXT];

    const int r   = threadIdx.x / TPR;        // row within block
    const int t   = threadIdx.x % TPR;        // thread within row
    const long long row = (long long)blockIdx.x * RPB + r;

    // ---- Load: one coalesced float4 per thread, deposit into extended array ----
    // e layout: e[0]=x[1], e[1]=x[0], e[2+k]=x[k] (k=0..511), e[514]=x[511], e[515]=x[510]
    const float4 v = reinterpret_cast<const float4*>(x + row * D)[t];
    float* er = e[r];
    er[4 * t + 2] = v.x;
    er[4 * t + 3] = v.y;
    er[4 * t + 4] = v.z;
    er[4 * t + 5] = v.w;
    if (t == 0) {                 // left symmetric boundary
        er[0] = v.y;              // x[1]
        er[1] = v.x;              // x[0]
    }
    if (t == TPR - 1) {           // right symmetric boundary (v = x[508..511])
        er[514] = v.w;            // x[511]
        er[515] = v.z;            // x[510]
    }
    __syncthreads();

    // ---- Compute: thread t produces z[4t .. 4t+3]  (p = 2t, 2t+1) ----
    // needs cA/cD at j = 2t, 2t+1, 2t+2  -> e[4t .. 4t+7], aligned LDS.128 x2
    const float4 a = *reinterpret_cast<const float4*>(er + 4 * t);
    const float4 b = *reinterpret_cast<const float4*>(er + 4 * t + 4);

    // analysis filters (stride-2 valid conv over extension)
    const float cA0 = fmaf(a.x, DL3, fmaf(a.y, DL2, fmaf(a.z, DL1, a.w * DL0)));
    const float cA1 = fmaf(a.z, DL3, fmaf(a.w, DL2, fmaf(b.x, DL1, b.y * DL0)));
    const float cA2 = fmaf(b.x, DL3, fmaf(b.y, DL2, fmaf(b.z, DL1, b.w * DL0)));

    float cD0 = fmaf(a.x, DH3, fmaf(a.y, DH2, fmaf(a.z, DH1, a.w * DH0)));
    float cD1 = fmaf(a.z, DH3, fmaf(a.w, DH2, fmaf(b.x, DH1, b.y * DH0)));
    float cD2 = fmaf(b.x, DH3, fmaf(b.y, DH2, fmaf(b.z, DH1, b.w * DH0)));

    // detail scaling by weight[0][j]  (weight is (2, 257); row 0 = first 257 floats)
    cD0 *= __ldg(weight + 2 * t);
    cD1 *= __ldg(weight + 2 * t + 1);
    cD2 *= __ldg(weight + 2 * t + 2);

    // synthesis (upsample-by-2 conv with rec filters), fused output
    float4 z;
    z.x = fmaf(RL2, cA0, fmaf(RL0, cA1, fmaf(RH2, cD0, RH0 * cD1)));  // m = 4t
    z.y = fmaf(RL3, cA0, fmaf(RL1, cA1, fmaf(RH3, cD0, RH1 * cD1)));  // m = 4t+1
    z.z = fmaf(RL2, cA1, fmaf(RL0, cA2, fmaf(RH2, cD1, RH0 * cD2)));  // m = 4t+2
    z.w = fmaf(RL3, cA1, fmaf(RL1, cA2, fmaf(RH3, cD1, RH1 * cD2)));  // m = 4t+3

    // leaky_relu(0.01)
    z.x = z.x > 0.0f ? z.x : 0.01f * z.x;
    z.y = z.y > 0.0f ? z.y : 0.01f * z.y;
    z.z = z.z > 0.0f ? z.z : 0.01f * z.z;
    z.w = z.w > 0.0f ? z.w : 0.01f * z.w;

    reinterpret_cast<float4*>(out + row * D)[t] = z;
}

extern "C" void kernel_launch(void* const* d_in, const int* in_sizes, int n_in,
                              void* d_out, int out_size)
{
    const float* x = (const float*)d_in[0];       // (B, 512) fp32
    const float* w = (const float*)d_in[1];       // (2, 257) fp32
    float* out = (float*)d_out;                   // (B, 512) fp32

    const int nrows = in_sizes[0] / D;            // 65536 (even; RPB=2 divides it)
    const int grid  = nrows / RPB;

    wavelet_db2_fused_kernel<<<grid, TPR * RPB>>>(x, w, out);
}

// round 2
// speedup vs baseline: 1.0374x; 1.0374x over previous
#include <cuda_runtime.h>

// db2 filter constants
#define DL0 (-0.12940952255092145f)
#define DL1 ( 0.22414386804185735f)
#define DL2 ( 0.836516303737469f)
#define DL3 ( 0.48296291314469025f)
#define DH0 (-0.48296291314469025f)
#define DH1 ( 0.836516303737469f)
#define DH2 (-0.22414386804185735f)
#define DH3 (-0.12940952255092145f)
#define RL0 ( 0.48296291314469025f)
#define RL1 ( 0.836516303737469f)
#define RL2 ( 0.22414386804185735f)
#define RL3 (-0.12940952255092145f)
#define RH0 (-0.12940952255092145f)
#define RH1 (-0.22414386804185735f)
#define RH2 ( 0.836516303737469f)
#define RH3 (-0.48296291314469025f)

static constexpr int D        = 512;  // row length (floats)
static constexpr int SEGS     = 4;    // 128-float segments per row (one warp each)
static constexpr int WARPS_PB = 8;    // warps per block
static constexpr int TPB      = WARPS_PB * 32;

// One warp handles one 128-float segment of a row.
// lane L owns x[col .. col+3] with col = 128*seg + 4*L.
// Stencil needs x[col-2 .. col+5]:
//   x[col-2], x[col-1] -> lane L-1's v.z, v.w  (shfl_up)
//   x[col+4], x[col+5] -> lane L+1's v.x, v.y  (shfl_down)
// Segment boundaries: lanes 0/31 fix up with 2 scalar global loads (L2 hits),
// row boundaries use the symmetric extension.
__global__ __launch_bounds__(TPB)
void wavelet_db2_shfl_kernel(const float* __restrict__ x,
                             const float* __restrict__ weight,
                             float* __restrict__ out)
{
    const int warp = threadIdx.x >> 5;
    const int lane = threadIdx.x & 31;

    const long long chunk = (long long)blockIdx.x * WARPS_PB + warp;
    const long long row   = chunk >> 2;          // chunk / SEGS
    const int       seg   = (int)(chunk & 3);

    const float* __restrict__ rowp = x + row * D;
    const int col = (seg << 7) + (lane << 2);    // 128*seg + 4*lane

    // ---- coalesced main load: 1x LDG.128 per thread ----
    const float4 v = *reinterpret_cast<const float4*>(rowp + col);

    // ---- halo via shuffles ----
    float xm2 = __shfl_up_sync(0xffffffffu, v.z, 1);   // x[col-2]
    float xm1 = __shfl_up_sync(0xffffffffu, v.w, 1);   // x[col-1]
    float xp4 = __shfl_down_sync(0xffffffffu, v.x, 1); // x[col+4]
    float xp5 = __shfl_down_sync(0xffffffffu, v.y, 1); // x[col+5]

    if (lane == 0) {
        if (seg == 0) { xm2 = v.y; xm1 = v.x; }        // symmetric left: x[1], x[0]
        else          { xm2 = __ldg(rowp + col - 2); xm1 = __ldg(rowp + col - 1); }
    }
    if (lane == 31) {
        if (seg == SEGS - 1) { xp4 = v.w; xp5 = v.z; } // symmetric right: x[511], x[510]
        else                 { xp4 = __ldg(rowp + col + 4); xp5 = __ldg(rowp + col + 5); }
    }

    // a = (x[col-2], x[col-1], x[col], x[col+1]),  b = (x[col+2], x[col+3], x[col+4], x[col+5])
    const float a0 = xm2, a1 = xm1, a2 = v.x, a3 = v.y;
    const float b0 = v.z, b1 = v.w, b2 = xp4, b3 = xp5;

    // ---- analysis (stride-2 valid conv over symmetric extension) ----
    const float cA0 = fmaf(a0, DL3, fmaf(a1, DL2, fmaf(a2, DL1, a3 * DL0)));
    const float cA1 = fmaf(a2, DL3, fmaf(a3, DL2, fmaf(b0, DL1, b1 * DL0)));
    const float cA2 = fmaf(b0, DL3, fmaf(b1, DL2, fmaf(b2, DL1, b3 * DL0)));

    float cD0 = fmaf(a0, DH3, fmaf(a1, DH2, fmaf(a2, DH1, a3 * DH0)));
    float cD1 = fmaf(a2, DH3, fmaf(a3, DH2, fmaf(b0, DH1, b1 * DH0)));
    float cD2 = fmaf(b0, DH3, fmaf(b1, DH2, fmaf(b2, DH1, b3 * DH0)));

    // ---- detail scaling: weight row 0, indices 2k, 2k+1, 2k+2 with k = col/4 ----
    const int k = col >> 2;
    const float2 w01 = __ldg(reinterpret_cast<const float2*>(weight) + k); // weight[2k], weight[2k+1]
    const float  w2  = __ldg(weight + 2 * k + 2);
    cD0 *= w01.x;
    cD1 *= w01.y;
    cD2 *= w2;

    // ---- synthesis + leaky ReLU ----
    float4 z;
    z.x = fmaf(RL2, cA0, fmaf(RL0, cA1, fmaf(RH2, cD0, RH0 * cD1)));
    z.y = fmaf(RL3, cA0, fmaf(RL1, cA1, fmaf(RH3, cD0, RH1 * cD1)));
    z.z = fmaf(RL2, cA1, fmaf(RL0, cA2, fmaf(RH2, cD1, RH0 * cD2)));
    z.w = fmaf(RL3, cA1, fmaf(RL1, cA2, fmaf(RH3, cD1, RH1 * cD2)));

    z.x = z.x > 0.0f ? z.x : 0.01f * z.x;
    z.y = z.y > 0.0f ? z.y : 0.01f * z.y;
    z.z = z.z > 0.0f ? z.z : 0.01f * z.z;
    z.w = z.w > 0.0f ? z.w : 0.01f * z.w;

    *reinterpret_cast<float4*>(out + row * D + col) = z;
}

extern "C" void kernel_launch(void* const* d_in, const int* in_sizes, int n_in,
                              void* d_out, int out_size)
{
    const float* x = (const float*)d_in[0];   // (B, 512) fp32
    const float* w = (const float*)d_in[1];   // (2, 257) fp32
    float* out = (float*)d_out;               // (B, 512) fp32

    const int nrows  = in_sizes[0] / D;                   // 65536
    const long long chunks = (long long)nrows * SEGS;     // 262144
    const int grid = (int)(chunks / WARPS_PB);            // 32768

    wavelet_db2_shfl_kernel<<<grid, TPB>>>(x, w, out);
}

// round 3
// speedup vs baseline: 1.1412x; 1.1000x over previous
#include <cuda_runtime.h>

// db2 filter constants
#define DL0 (-0.12940952255092145f)
#define DL1 ( 0.22414386804185735f)
#define DL2 ( 0.836516303737469f)
#define DL3 ( 0.48296291314469025f)
#define DH0 (-0.48296291314469025f)
#define DH1 ( 0.836516303737469f)
#define DH2 (-0.22414386804185735f)
#define DH3 (-0.12940952255092145f)
#define RL0 ( 0.48296291314469025f)
#define RL1 ( 0.836516303737469f)
#define RL2 ( 0.22414386804185735f)
#define RL3 (-0.12940952255092145f)
#define RH0 (-0.12940952255092145f)
#define RH1 (-0.22414386804185735f)
#define RH2 ( 0.836516303737469f)
#define RH3 (-0.48296291314469025f)

static constexpr int D        = 512;  // row length (floats)
static constexpr int SEGS     = 2;    // 256-float segments per row (one warp each)
static constexpr int WARPS_PB = 8;    // warps per block
static constexpr int TPB      = WARPS_PB * 32;

// One warp handles a 256-float half-row. Lane L owns x[c .. c+7], c = 256*seg + 8*L.
// Stencil for 8 outputs needs s[0..11] = x[c-2 .. c+9]:
//   s0,s1  = lane L-1's v1.z, v1.w   (shfl_up)
//   s10,s11= lane L+1's v0.x, v0.y   (shfl_down)
// Lane 0 / lane 31 fix up at segment boundaries (L2-hit scalar loads) or use
// the symmetric row extension.
__global__ __launch_bounds__(TPB)
void wavelet_db2_shfl8_kernel(const float* __restrict__ x,
                              const float* __restrict__ weight,
                              float* __restrict__ out)
{
    const int warp = threadIdx.x >> 5;
    const int lane = threadIdx.x & 31;

    const long long chunk = (long long)blockIdx.x * WARPS_PB + warp;
    const long long row   = chunk >> 1;
    const int       seg   = (int)(chunk & 1);

    const float* __restrict__ rowp = x + row * D;
    const int c = (seg << 8) + (lane << 3);   // 256*seg + 8*lane

    // ---- two independent coalesced LDG.128 (MLP=2), streaming ----
    const float4 v0 = __ldcs(reinterpret_cast<const float4*>(rowp + c));
    const float4 v1 = __ldcs(reinterpret_cast<const float4*>(rowp + c + 4));

    // ---- halo via 4 shuffles (for 8 outputs) ----
    float s0  = __shfl_up_sync(0xffffffffu, v1.z, 1);   // x[c-2]
    float s1  = __shfl_up_sync(0xffffffffu, v1.w, 1);   // x[c-1]
    float s10 = __shfl_down_sync(0xffffffffu, v0.x, 1); // x[c+8]
    float s11 = __shfl_down_sync(0xffffffffu, v0.y, 1); // x[c+9]

    if (lane == 0) {
        if (seg == 0) { s0 = v0.y; s1 = v0.x; }                       // x[1], x[0]
        else          { s0 = __ldg(rowp + c - 2); s1 = __ldg(rowp + c - 1); }
    }
    if (lane == 31) {
        if (seg == SEGS - 1) { s10 = v1.w; s11 = v1.z; }              // x[511], x[510]
        else                 { s10 = __ldg(rowp + c + 8); s11 = __ldg(rowp + c + 9); }
    }

    const float s2 = v0.x, s3 = v0.y, s4 = v0.z, s5 = v0.w;
    const float s6 = v1.x, s7 = v1.y, s8 = v1.z, s9 = v1.w;
    const float s[12] = {s0, s1, s2, s3, s4, s5, s6, s7, s8, s9, s10, s11};

    // ---- analysis: cA/cD at j = c/2 .. c/2+4 ----
    float cA[5], cD[5];
#pragma unroll
    for (int i = 0; i < 5; i++) {
        cA[i] = fmaf(s[2*i], DL3, fmaf(s[2*i+1], DL2, fmaf(s[2*i+2], DL1, s[2*i+3] * DL0)));
        cD[i] = fmaf(s[2*i], DH3, fmaf(s[2*i+1], DH2, fmaf(s[2*i+2], DH1, s[2*i+3] * DH0)));
    }

    // ---- detail scaling: weight row0[k .. k+4], k = c/2 (multiple of 4) ----
    const int k = c >> 1;
    const float4 wv = __ldg(reinterpret_cast<const float4*>(weight + k));
    const float  w4 = __ldg(weight + k + 4);
    cD[0] *= wv.x; cD[1] *= wv.y; cD[2] *= wv.z; cD[3] *= wv.w; cD[4] *= w4;

    // ---- synthesis + leaky ReLU, two float4 stores ----
    float z[8];
#pragma unroll
    for (int i = 0; i < 4; i++) {
        float ze = fmaf(RL2, cA[i], fmaf(RL0, cA[i+1], fmaf(RH2, cD[i], RH0 * cD[i+1])));
        float zo = fmaf(RL3, cA[i], fmaf(RL1, cA[i+1], fmaf(RH3, cD[i], RH1 * cD[i+1])));
        z[2*i]   = ze > 0.0f ? ze : 0.01f * ze;
        z[2*i+1] = zo > 0.0f ? zo : 0.01f * zo;
    }

    float* op = out + row * D + c;
    __stcs(reinterpret_cast<float4*>(op),     make_float4(z[0], z[1], z[2], z[3]));
    __stcs(reinterpret_cast<float4*>(op + 4), make_float4(z[4], z[5], z[6], z[7]));
}

extern "C" void kernel_launch(void* const* d_in, const int* in_sizes, int n_in,
                              void* d_out, int out_size)
{
    const float* x = (const float*)d_in[0];   // (B, 512) fp32
    const float* w = (const float*)d_in[1];   // (2, 257) fp32
    float* out = (float*)d_out;               // (B, 512) fp32

    const int nrows = in_sizes[0] / D;                 // 65536
    const long long chunks = (long long)nrows * SEGS;  // 131072
    const int grid = (int)(chunks / WARPS_PB);         // 16384

    wavelet_db2_shfl8_kernel<<<grid, TPB>>>(x, w, out);
}